// round 6
// baseline (speedup 1.0000x reference)
#include <cuda_runtime.h>

// QuantBatchedEmbeddingBag: T=8 tables, R=200000 rows, D=128, B=2048 bags/table.
// Inputs (metadata order):
//   d_in[0] indices     int32 [N = 524288]
//   d_in[1] offsets     int32 [T*B + 1 = 16385]  (CSR bag boundaries, feature-major)
//   d_in[2] qweights    int32 [T, R, D]          (int8 codes in [0,256) stored as int32)
//   d_in[3] scale_shift float32 [T, R, 2]
// Output: float32 [B, T*D] = [2048, 1024], out[b, t*D + d] = pooled[t*B + b, d]

#define T_TABLES 8
#define R_ROWS   200000
#define D_DIM    128
#define B_BATCH  2048
#define NUM_BAGS (T_TABLES * B_BATCH)

__global__ __launch_bounds__(256, 8)
void embbag_kernel(const int*   __restrict__ indices,
                   const int*   __restrict__ offsets,
                   const int*   __restrict__ qweights,
                   const float* __restrict__ scale_shift,
                   float*       __restrict__ out)
{
    const int gwarp = (blockIdx.x * blockDim.x + threadIdx.x) >> 5;  // bag id = seg
    const int lane  = threadIdx.x & 31;
    if (gwarp >= NUM_BAGS) return;

    const int t = gwarp / B_BATCH;   // table
    const int b = gwarp % B_BATCH;   // batch row

    const int start = offsets[gwarp];
    const int end   = offsets[gwarp + 1];

    // Per-table bases. Rows are 128 int32 = 512B; each lane reads int4 at lane*16B.
    const int4*   qbase  = reinterpret_cast<const int4*>(
                               qweights + (long long)t * R_ROWS * D_DIM);
    const float2* ssbase = reinterpret_cast<const float2*>(scale_shift)
                               + (long long)t * R_ROWS;

    float4 acc = make_float4(0.f, 0.f, 0.f, 0.f);
    float  shift_sum = 0.f;   // per-row shift is identical across dims: hoist + reduce

    for (int base = start; base < end; base += 32) {
        const int n = min(32, end - base);

        // Coalesced chunk-load of up to 32 indices, one per lane, then each lane
        // gathers ITS row's {scale, shift} -> 32 independent loads in flight at once.
        const int   myidx = (lane < n) ? __ldg(indices + base + lane) : 0;
        float2 myss = make_float2(0.f, 0.f);
        if (lane < n) myss = __ldg(ssbase + myidx);

        // Warp-reduce the shifts once per chunk (invalid lanes contribute 0).
        float sh = myss.y;
        #pragma unroll
        for (int d = 16; d > 0; d >>= 1)
            sh += __shfl_xor_sync(0xffffffffu, sh, d);
        shift_sum += sh;

        // Row-gather + dequant-accumulate. One memory op per iteration; deep
        // unroll lets ptxas front-batch many independent LDG.128s (high MLP).
        #pragma unroll 32
        for (int r = 0; r < n; r++) {
            const int   row   = __shfl_sync(0xffffffffu, myidx,  r);
            const float scale = __shfl_sync(0xffffffffu, myss.x, r);
            const int4  q = __ldg(qbase + (long long)row * (D_DIM / 4) + lane);
            acc.x = fmaf((float)q.x, scale, acc.x);
            acc.y = fmaf((float)q.y, scale, acc.y);
            acc.z = fmaf((float)q.z, scale, acc.z);
            acc.w = fmaf((float)q.w, scale, acc.w);
        }
    }

    acc.x += shift_sum;
    acc.y += shift_sum;
    acc.z += shift_sum;
    acc.w += shift_sum;

    // out[b, t*D + lane*4 .. +3]  -> float4 element index (b*T + t)*32 + lane
    reinterpret_cast<float4*>(out)[((long long)b * T_TABLES + t) * (D_DIM / 4) + lane] = acc;
}

extern "C" void kernel_launch(void* const* d_in, const int* in_sizes, int n_in,
                              void* d_out, int out_size)
{
    const int*   indices     = (const int*)  d_in[0];
    const int*   offsets     = (const int*)  d_in[1];
    const int*   qweights    = (const int*)  d_in[2];
    const float* scale_shift = (const float*)d_in[3];
    float*       out         = (float*)      d_out;

    const int threads = 256;                       // 8 warps -> 8 bags per CTA
    const int blocks  = (NUM_BAGS * 32 + threads - 1) / threads;  // 2048
    embbag_kernel<<<blocks, threads>>>(indices, offsets, qweights, scale_shift, out);
}

// round 7
// speedup vs baseline: 1.5570x; 1.5570x over previous
#include <cuda_runtime.h>

// QuantBatchedEmbeddingBag: T=8 tables, R=200000 rows, D=128, B=2048 bags/table.
// Inputs (metadata order):
//   d_in[0] indices     int32 [N = 524288]
//   d_in[1] offsets     int32 [T*B + 1 = 16385]  (CSR bag boundaries, feature-major)
//   d_in[2] qweights    int32 [T, R, D]          (int8 codes in [0,256) stored as int32)
//   d_in[3] scale_shift float32 [T, R, 2]
// Output: float32 [B, T*D] = [2048, 1024], out[b, t*D + d] = pooled[t*B + b, d]

#define T_TABLES 8
#define R_ROWS   200000
#define D_DIM    128
#define B_BATCH  2048
#define NUM_BAGS (T_TABLES * B_BATCH)
#define PIPE     8   // explicit gather pipeline depth (8 x int4 = 32 regs)

__global__ __launch_bounds__(256, 4)   // 64 regs/thread: room for the pipeline
void embbag_kernel(const int*   __restrict__ indices,
                   const int*   __restrict__ offsets,
                   const int*   __restrict__ qweights,
                   const float* __restrict__ scale_shift,
                   float*       __restrict__ out)
{
    const int gwarp = (blockIdx.x * blockDim.x + threadIdx.x) >> 5;  // bag id = seg
    const int lane  = threadIdx.x & 31;
    if (gwarp >= NUM_BAGS) return;

    const int t = gwarp / B_BATCH;   // table
    const int b = gwarp % B_BATCH;   // batch row

    const int start = offsets[gwarp];
    const int end   = offsets[gwarp + 1];

    // Per-table bases. Rows are 128 int32 = 512B; each lane reads int4 at lane*16B.
    const int4*   qbase  = reinterpret_cast<const int4*>(
                               qweights + (long long)t * R_ROWS * D_DIM);
    const float2* ssbase = reinterpret_cast<const float2*>(scale_shift)
                               + (long long)t * R_ROWS;

    float4 acc = make_float4(0.f, 0.f, 0.f, 0.f);
    float  shift_sum = 0.f;   // per-row shift is identical across dims: hoist + reduce

    for (int base = start; base < end; base += 32) {
        const int n = min(32, end - base);

        // Coalesced chunk-load of up to 32 indices, one per lane; each lane then
        // gathers ITS row's {scale, shift} -> 32 independent 8B loads in flight.
        const int myidx = (lane < n) ? __ldg(indices + base + lane) : 0;
        float2 myss = make_float2(0.f, 0.f);
        if (lane < n) myss = __ldg(ssbase + myidx);

        // Warp-reduce the shifts once per chunk (invalid lanes contribute 0).
        float sh = myss.y;
        #pragma unroll
        for (int d = 16; d > 0; d >>= 1)
            sh += __shfl_xor_sync(0xffffffffu, sh, d);
        shift_sum += sh;

        // Row gather in groups of PIPE: issue ALL PIPE independent LDG.128s
        // before any FMA consumes them -> guaranteed per-warp MLP = PIPE.
        for (int g = 0; g < n; g += PIPE) {
            const int m = min(PIPE, n - g);
            int4  q[PIPE];
            float sc[PIPE];
            #pragma unroll
            for (int j = 0; j < PIPE; j++) {
                if (j < m) {
                    const int row = __shfl_sync(0xffffffffu, myidx,  g + j);
                    sc[j]         = __shfl_sync(0xffffffffu, myss.x, g + j);
                    q[j] = __ldg(qbase + (long long)row * (D_DIM / 4) + lane);
                }
            }
            #pragma unroll
            for (int j = 0; j < PIPE; j++) {
                if (j < m) {
                    acc.x = fmaf((float)q[j].x, sc[j], acc.x);
                    acc.y = fmaf((float)q[j].y, sc[j], acc.y);
                    acc.z = fmaf((float)q[j].z, sc[j], acc.z);
                    acc.w = fmaf((float)q[j].w, sc[j], acc.w);
                }
            }
        }
    }

    acc.x += shift_sum;
    acc.y += shift_sum;
    acc.z += shift_sum;
    acc.w += shift_sum;

    // out[b, t*D + lane*4 .. +3]  -> float4 element index (b*T + t)*32 + lane
    reinterpret_cast<float4*>(out)[((long long)b * T_TABLES + t) * (D_DIM / 4) + lane] = acc;
}

extern "C" void kernel_launch(void* const* d_in, const int* in_sizes, int n_in,
                              void* d_out, int out_size)
{
    const int*   indices     = (const int*)  d_in[0];
    const int*   offsets     = (const int*)  d_in[1];
    const int*   qweights    = (const int*)  d_in[2];
    const float* scale_shift = (const float*)d_in[3];
    float*       out         = (float*)      d_out;

    const int threads = 256;                                      // 8 warps/CTA
    const int blocks  = (NUM_BAGS * 32 + threads - 1) / threads;  // 2048
    embbag_kernel<<<blocks, threads>>>(indices, offsets, qweights, scale_shift, out);
}

// round 8
// speedup vs baseline: 1.9840x; 1.2742x over previous
#include <cuda_runtime.h>

// QuantBatchedEmbeddingBag: T=8 tables, R=200000 rows, D=128, B=2048 bags/table.
// Inputs (metadata order):
//   d_in[0] indices     int32 [N = 524288]
//   d_in[1] offsets     int32 [T*B + 1 = 16385]  (CSR bag boundaries, feature-major)
//   d_in[2] qweights    int32 [T, R, D]          (int8 codes in [0,256) stored as int32)
//   d_in[3] scale_shift float32 [T, R, 2]
// Output: float32 [B, T*D] = [2048, 1024], out[b, t*D + d] = pooled[t*B + b, d]

#define T_TABLES 8
#define R_ROWS   200000
#define D_DIM    128
#define B_BATCH  2048
#define NUM_BAGS (T_TABLES * B_BATCH)
#define PIPE     8   // explicit gather pipeline depth (8 x int4 = 32 regs)
#define WPB      4   // warps cooperating per bag

__global__ __launch_bounds__(WPB * 32, 8)   // 64 regs/thread, 8 CTAs/SM
void embbag_kernel(const int*   __restrict__ indices,
                   const int*   __restrict__ offsets,
                   const int*   __restrict__ qweights,
                   const float* __restrict__ scale_shift,
                   float*       __restrict__ out)
{
    const int bag  = blockIdx.x;           // one CTA per bag
    const int s    = threadIdx.x >> 5;     // sub-warp id within bag (0..3)
    const int lane = threadIdx.x & 31;

    const int t = bag / B_BATCH;           // table
    const int b = bag % B_BATCH;           // batch row

    const int start = offsets[bag];
    const int len   = offsets[bag + 1] - start;

    // Per-table bases. Rows are 128 int32 = 512B; each lane reads int4 at lane*16B.
    const int4*   qbase  = reinterpret_cast<const int4*>(
                               qweights + (long long)t * R_ROWS * D_DIM);
    const float2* ssbase = reinterpret_cast<const float2*>(scale_shift)
                               + (long long)t * R_ROWS;

    float4 acc = make_float4(0.f, 0.f, 0.f, 0.f);
    float  shift_sum = 0.f;   // per-row shift is identical across dims: hoist + reduce

    // Sub-warp s owns bag rows s, s+WPB, s+2*WPB, ... -> balanced to +-1 row.
    const int count = (len > s) ? (len - s + WPB - 1) / WPB : 0;

    for (int jbase = 0; jbase < count; jbase += 32) {
        const int n = min(32, count - jbase);   // valid lanes form a prefix
        const int j = jbase + lane;
        const bool v = (j < count);

        // Chunk-load this sub-warp's indices (stride WPB*4B between lanes),
        // then each lane gathers ITS row's {scale, shift}: 32 loads in flight.
        const int myidx = v ? __ldg(indices + start + s + WPB * j) : 0;
        float2 myss = make_float2(0.f, 0.f);
        if (v) myss = __ldg(ssbase + myidx);

        // Warp-reduce the shifts once per chunk (invalid lanes contribute 0).
        float sh = myss.y;
        #pragma unroll
        for (int d = 16; d > 0; d >>= 1)
            sh += __shfl_xor_sync(0xffffffffu, sh, d);
        shift_sum += sh;

        // Row gather in groups of PIPE: all PIPE independent LDG.128s issued
        // before any FMA consumes them -> guaranteed per-warp MLP = PIPE.
        for (int g = 0; g < n; g += PIPE) {
            const int m = min(PIPE, n - g);
            int4  q[PIPE];
            float sc[PIPE];
            #pragma unroll
            for (int k = 0; k < PIPE; k++) {
                if (k < m) {
                    const int row = __shfl_sync(0xffffffffu, myidx,  g + k);
                    sc[k]         = __shfl_sync(0xffffffffu, myss.x, g + k);
                    q[k] = __ldg(qbase + (long long)row * (D_DIM / 4) + lane);
                }
            }
            #pragma unroll
            for (int k = 0; k < PIPE; k++) {
                if (k < m) {
                    acc.x = fmaf((float)q[k].x, sc[k], acc.x);
                    acc.y = fmaf((float)q[k].y, sc[k], acc.y);
                    acc.z = fmaf((float)q[k].z, sc[k], acc.z);
                    acc.w = fmaf((float)q[k].w, sc[k], acc.w);
                }
            }
        }
    }

    acc.x += shift_sum;
    acc.y += shift_sum;
    acc.z += shift_sum;
    acc.w += shift_sum;

    // Combine the WPB partial accumulators through shared memory (no atomics).
    __shared__ float4 red[WPB][32];
    red[s][lane] = acc;
    __syncthreads();

    if (s == 0) {
        float4 a0 = red[0][lane];
        float4 a1 = red[1][lane];
        float4 a2 = red[2][lane];
        float4 a3 = red[3][lane];
        a0.x += a1.x + a2.x + a3.x;
        a0.y += a1.y + a2.y + a3.y;
        a0.z += a1.z + a2.z + a3.z;
        a0.w += a1.w + a2.w + a3.w;
        // out[b, t*D + lane*4 .. +3] -> float4 element index (b*T + t)*32 + lane
        reinterpret_cast<float4*>(out)[((long long)b * T_TABLES + t) * (D_DIM / 4) + lane] = a0;
    }
}

extern "C" void kernel_launch(void* const* d_in, const int* in_sizes, int n_in,
                              void* d_out, int out_size)
{
    const int*   indices     = (const int*)  d_in[0];
    const int*   offsets     = (const int*)  d_in[1];
    const int*   qweights    = (const int*)  d_in[2];
    const float* scale_shift = (const float*)d_in[3];
    float*       out         = (float*)      d_out;

    embbag_kernel<<<NUM_BAGS, WPB * 32>>>(indices, offsets, qweights, scale_shift, out);
}

// round 9
// speedup vs baseline: 2.0441x; 1.0303x over previous
#include <cuda_runtime.h>

// QuantBatchedEmbeddingBag: T=8 tables, R=200000 rows, D=128, B=2048 bags/table.
// Inputs (metadata order):
//   d_in[0] indices     int32 [N = 524288]
//   d_in[1] offsets     int32 [T*B + 1 = 16385]  (CSR bag boundaries, feature-major)
//   d_in[2] qweights    int32 [T, R, D]          (int8 codes in [0,256) stored as int32)
//   d_in[3] scale_shift float32 [T, R, 2]
// Output: float32 [B, T*D] = [2048, 1024], out[b, t*D + d] = pooled[t*B + b, d]

#define T_TABLES 8
#define R_ROWS   200000
#define D_DIM    128
#define B_BATCH  2048
#define NUM_BAGS (T_TABLES * B_BATCH)
#define PIPE     6   // gather pipeline depth (6 x int4 = 24 regs)
#define WPB      4   // warps cooperating per bag

__global__ __launch_bounds__(WPB * 32, 10)   // <=51 regs -> 10 CTAs/SM = 40 warps
void embbag_kernel(const int*   __restrict__ indices,
                   const int*   __restrict__ offsets,
                   const int*   __restrict__ qweights,
                   const float* __restrict__ scale_shift,
                   float*       __restrict__ out)
{
    const int bag  = blockIdx.x;           // one CTA per bag
    const int s    = threadIdx.x >> 5;     // sub-warp id within bag (0..3)
    const int lane = threadIdx.x & 31;

    const int t = bag / B_BATCH;           // table
    const int b = bag % B_BATCH;           // batch row

    const int start = offsets[bag];
    const int len   = offsets[bag + 1] - start;

    // Per-table bases. Rows are 128 int32 = 512B; each lane reads int4 at lane*16B.
    const int4*   qbase  = reinterpret_cast<const int4*>(
                               qweights + (long long)t * R_ROWS * D_DIM);
    const float2* ssbase = reinterpret_cast<const float2*>(scale_shift)
                               + (long long)t * R_ROWS;

    float4 acc = make_float4(0.f, 0.f, 0.f, 0.f);
    float  shift_sum = 0.f;   // per-row shift is identical across dims: hoist + reduce

    // Sub-warp s owns bag rows s, s+WPB, s+2*WPB, ... -> balanced to +-1 row.
    const int count = (len > s) ? (len - s + WPB - 1) / WPB : 0;

    for (int jbase = 0; jbase < count; jbase += 32) {
        const int n = min(32, count - jbase);   // valid lanes form a prefix
        const int j = jbase + lane;
        const bool v = (j < count);

        // Chunk-load this sub-warp's indices; rows depend ONLY on these, so the
        // row gathers below start as soon as this load lands.
        const int myidx = v ? __ldg(indices + start + s + WPB * j) : 0;

        // Scale/shift gather: issued right away, but consumed only at FMA time /
        // chunk end -> its latency overlaps the row-gather stream.
        float2 myss = make_float2(0.f, 0.f);
        if (v) myss = __ldg(ssbase + myidx);

        // Row gather in groups of PIPE: all PIPE independent LDG.128s issued
        // before any FMA consumes them -> per-warp MLP = PIPE. Scale is pulled
        // by shuffle at consume time (no sc[] array -> fewer registers).
        for (int g = 0; g < n; g += PIPE) {
            const int m = min(PIPE, n - g);
            int4 q[PIPE];
            #pragma unroll
            for (int k = 0; k < PIPE; k++) {
                if (k < m) {
                    const int row = __shfl_sync(0xffffffffu, myidx, g + k);
                    q[k] = __ldg(qbase + (long long)row * (D_DIM / 4) + lane);
                }
            }
            #pragma unroll
            for (int k = 0; k < PIPE; k++) {
                if (k < m) {
                    const float sc = __shfl_sync(0xffffffffu, myss.x, g + k);
                    acc.x = fmaf((float)q[k].x, sc, acc.x);
                    acc.y = fmaf((float)q[k].y, sc, acc.y);
                    acc.z = fmaf((float)q[k].z, sc, acc.z);
                    acc.w = fmaf((float)q[k].w, sc, acc.w);
                }
            }
        }

        // Warp-reduce the shifts once per chunk (invalid lanes contribute 0).
        float sh = myss.y;
        #pragma unroll
        for (int d = 16; d > 0; d >>= 1)
            sh += __shfl_xor_sync(0xffffffffu, sh, d);
        shift_sum += sh;
    }

    acc.x += shift_sum;
    acc.y += shift_sum;
    acc.z += shift_sum;
    acc.w += shift_sum;

    // Combine the WPB partial accumulators through shared memory (no atomics).
    __shared__ float4 red[WPB][32];
    red[s][lane] = acc;
    __syncthreads();

    if (s == 0) {
        float4 a0 = red[0][lane];
        float4 a1 = red[1][lane];
        float4 a2 = red[2][lane];
        float4 a3 = red[3][lane];
        a0.x += a1.x + a2.x + a3.x;
        a0.y += a1.y + a2.y + a3.y;
        a0.z += a1.z + a2.z + a3.z;
        a0.w += a1.w + a2.w + a3.w;
        // out[b, t*D + lane*4 .. +3] -> float4 element index (b*T + t)*32 + lane
        reinterpret_cast<float4*>(out)[((long long)b * T_TABLES + t) * (D_DIM / 4) + lane] = a0;
    }
}

extern "C" void kernel_launch(void* const* d_in, const int* in_sizes, int n_in,
                              void* d_out, int out_size)
{
    const int*   indices     = (const int*)  d_in[0];
    const int*   offsets     = (const int*)  d_in[1];
    const int*   qweights    = (const int*)  d_in[2];
    const float* scale_shift = (const float*)d_in[3];
    float*       out         = (float*)      d_out;

    embbag_kernel<<<NUM_BAGS, WPB * 32>>>(indices, offsets, qweights, scale_shift, out);
}